// round 1
// baseline (speedup 1.0000x reference)
#include <cuda_runtime.h>

// FastSNN: proj GEMM (fp32) -> LIF scan over T -> decoder
// Shapes: T=500, B=128, W=256, F=512, C=10
//
// Phase 1: g_proj[T*B, F] = X[T*B, W] @ Wt[F, W]^T   (classic 128x128x16 SGEMM,
//          8x8 register tiles, double-buffered SMEM)
// Phase 2: per-(b,f) LIF scan over t (trace/u/spike-count), fused decoder
//          reduction per batch row.

#define TT 500
#define BB 128
#define WW 256
#define FF 512
#define CC 10
#define MM (TT * BB)   // 64000 rows

// 131 MB scratch for proj (static device array: allocation-free per harness rules)
__device__ float g_proj[(size_t)TT * BB * FF];

// ---------------------------------------------------------------------------
// GEMM: C[M,N] = A[M,K] * B[N,K]^T,  M=64000, N=512, K=256  (all exact tiles)
// ---------------------------------------------------------------------------
#define BM 128
#define BN 128
#define BK 16
#define SPAD 132   // smem row stride in floats (16B-aligned, reduces store conflicts)

__global__ __launch_bounds__(256, 2)
void gemm_kernel(const float* __restrict__ A, const float* __restrict__ B) {
    __shared__ float As[2][BK * SPAD];
    __shared__ float Bs[2][BK * SPAD];

    const int tid = threadIdx.x;
    const int tx  = tid & 15;     // 0..15  -> N direction
    const int ty  = tid >> 4;     // 0..15  -> M direction
    const int m0  = blockIdx.y * BM;
    const int n0  = blockIdx.x * BN;

    // global load mapping: each thread loads 2 float4 of A and 2 float4 of B per stage
    const int r0 = tid >> 2;      // 0..63 (row within half-tile)
    const int q  = tid & 3;       // which float4 along k (0..3)

    const float* gA0 = A + (size_t)(m0 + r0)      * WW + q * 4;
    const float* gA1 = A + (size_t)(m0 + r0 + 64) * WW + q * 4;
    const float* gB0 = B + (size_t)(n0 + r0)      * WW + q * 4;
    const float* gB1 = B + (size_t)(n0 + r0 + 64) * WW + q * 4;

    float acc[8][8];
#pragma unroll
    for (int i = 0; i < 8; i++)
#pragma unroll
        for (int j = 0; j < 8; j++) acc[i][j] = 0.0f;

    // prologue: load stage 0
    float4 a0 = *(const float4*)(gA0);
    float4 a1 = *(const float4*)(gA1);
    float4 b0 = *(const float4*)(gB0);
    float4 b1 = *(const float4*)(gB1);

    int buf = 0;
    {
        const int kb = q * 4;
        As[0][(kb + 0) * SPAD + r0]      = a0.x;
        As[0][(kb + 1) * SPAD + r0]      = a0.y;
        As[0][(kb + 2) * SPAD + r0]      = a0.z;
        As[0][(kb + 3) * SPAD + r0]      = a0.w;
        As[0][(kb + 0) * SPAD + r0 + 64] = a1.x;
        As[0][(kb + 1) * SPAD + r0 + 64] = a1.y;
        As[0][(kb + 2) * SPAD + r0 + 64] = a1.z;
        As[0][(kb + 3) * SPAD + r0 + 64] = a1.w;
        Bs[0][(kb + 0) * SPAD + r0]      = b0.x;
        Bs[0][(kb + 1) * SPAD + r0]      = b0.y;
        Bs[0][(kb + 2) * SPAD + r0]      = b0.z;
        Bs[0][(kb + 3) * SPAD + r0]      = b0.w;
        Bs[0][(kb + 0) * SPAD + r0 + 64] = b1.x;
        Bs[0][(kb + 1) * SPAD + r0 + 64] = b1.y;
        Bs[0][(kb + 2) * SPAD + r0 + 64] = b1.z;
        Bs[0][(kb + 3) * SPAD + r0 + 64] = b1.w;
    }
    __syncthreads();

    for (int k0 = 0; k0 < WW; k0 += BK) {
        const bool has_next = (k0 + BK) < WW;
        // prefetch next stage into registers (latency hidden by compute below)
        if (has_next) {
            a0 = *(const float4*)(gA0 + k0 + BK);
            a1 = *(const float4*)(gA1 + k0 + BK);
            b0 = *(const float4*)(gB0 + k0 + BK);
            b1 = *(const float4*)(gB1 + k0 + BK);
        }

        // compute on current stage
#pragma unroll
        for (int kk = 0; kk < BK; kk++) {
            float af[8], bf[8];
            *(float4*)(af)     = *(const float4*)&As[buf][kk * SPAD + ty * 4];
            *(float4*)(af + 4) = *(const float4*)&As[buf][kk * SPAD + 64 + ty * 4];
            *(float4*)(bf)     = *(const float4*)&Bs[buf][kk * SPAD + tx * 4];
            *(float4*)(bf + 4) = *(const float4*)&Bs[buf][kk * SPAD + 64 + tx * 4];
#pragma unroll
            for (int i = 0; i < 8; i++)
#pragma unroll
                for (int j = 0; j < 8; j++)
                    acc[i][j] += af[i] * bf[j];
        }

        // store next stage into the other buffer
        if (has_next) {
            const int nb = buf ^ 1;
            const int kb = q * 4;
            As[nb][(kb + 0) * SPAD + r0]      = a0.x;
            As[nb][(kb + 1) * SPAD + r0]      = a0.y;
            As[nb][(kb + 2) * SPAD + r0]      = a0.z;
            As[nb][(kb + 3) * SPAD + r0]      = a0.w;
            As[nb][(kb + 0) * SPAD + r0 + 64] = a1.x;
            As[nb][(kb + 1) * SPAD + r0 + 64] = a1.y;
            As[nb][(kb + 2) * SPAD + r0 + 64] = a1.z;
            As[nb][(kb + 3) * SPAD + r0 + 64] = a1.w;
            Bs[nb][(kb + 0) * SPAD + r0]      = b0.x;
            Bs[nb][(kb + 1) * SPAD + r0]      = b0.y;
            Bs[nb][(kb + 2) * SPAD + r0]      = b0.z;
            Bs[nb][(kb + 3) * SPAD + r0]      = b0.w;
            Bs[nb][(kb + 0) * SPAD + r0 + 64] = b1.x;
            Bs[nb][(kb + 1) * SPAD + r0 + 64] = b1.y;
            Bs[nb][(kb + 2) * SPAD + r0 + 64] = b1.z;
            Bs[nb][(kb + 3) * SPAD + r0 + 64] = b1.w;
        }
        __syncthreads();
        buf ^= 1;
    }

    // epilogue: write 8x8 tile as float4s
#pragma unroll
    for (int i = 0; i < 8; i++) {
        const int m = m0 + ((i < 4) ? (ty * 4 + i) : (64 + ty * 4 + (i - 4)));
        float* cp = g_proj + (size_t)m * FF + n0;
        float4 v0 = make_float4(acc[i][0], acc[i][1], acc[i][2], acc[i][3]);
        float4 v1 = make_float4(acc[i][4], acc[i][5], acc[i][6], acc[i][7]);
        *(float4*)(cp + tx * 4)      = v0;
        *(float4*)(cp + 64 + tx * 4) = v1;
    }
}

// ---------------------------------------------------------------------------
// LIF scan + fused decoder. One CTA per batch row b, thread f owns state (b,f).
// ---------------------------------------------------------------------------
__global__ __launch_bounds__(512)
void scan_decoder_kernel(const float* __restrict__ dec_w,
                         const float* __restrict__ dec_b,
                         float* __restrict__ out) {
    const int b = blockIdx.x;
    const int f = threadIdx.x;
    const float* pp = g_proj + (size_t)b * FF + f;

    float u = 0.0f, trace = 0.0f, cnt = 0.0f;

    // 500 = 50 chunks of 10; grouped loads give MLP=10 per thread
#pragma unroll 1
    for (int t0 = 0; t0 < TT; t0 += 10) {
        float v[10];
#pragma unroll
        for (int i = 0; i < 10; i++)
            v[i] = pp[(size_t)(t0 + i) * (BB * FF)];
#pragma unroll
        for (int i = 0; i < 10; i++) {
            trace = 0.95f * trace + v[i];
            u = 0.9f * u + trace;
            if (u > 1.0f) { cnt += 1.0f; u = 0.0f; }
        }
    }

    // decoder: out[b,c] = sum_f cnt[b,f] * dec_w[c,f] + dec_b[c]
    __shared__ float sred[512];
    for (int c = 0; c < CC; c++) {
        sred[f] = cnt * dec_w[c * FF + f];
        __syncthreads();
#pragma unroll
        for (int s = 256; s > 0; s >>= 1) {
            if (f < s) sred[f] += sred[f + s];
            __syncthreads();
        }
        if (f == 0) out[b * CC + c] = sred[0] + dec_b[c];
        __syncthreads();
    }
}

// ---------------------------------------------------------------------------
extern "C" void kernel_launch(void* const* d_in, const int* in_sizes, int n_in,
                              void* d_out, int out_size) {
    const float* x     = (const float*)d_in[0];  // [T,B,W] = [500,128,256]
    const float* wts   = (const float*)d_in[1];  // [F,W]   = [512,256]
    const float* dec_w = (const float*)d_in[2];  // [C,F]   = [10,512]
    const float* dec_b = (const float*)d_in[3];  // [C]     = [10]
    float* out = (float*)d_out;                  // [B,C]   = [128,10]

    (void)in_sizes; (void)n_in; (void)out_size;

    dim3 gemm_grid(FF / BN, MM / BM);   // (4, 500)
    gemm_kernel<<<gemm_grid, 256>>>(x, wts);

    scan_decoder_kernel<<<BB, 512>>>(dec_w, dec_b, out);
}

// round 3
// speedup vs baseline: 1.0711x; 1.0711x over previous
#include <cuda_runtime.h>
#include <cstdint>

// FastSNN: fp32 GEMM via 3xTF32 mma.sync (HMMA) -> LIF scan -> decoder
// proj[m,f] = sum_w X[m,w] * Wt[f,w],  M=64000, N(F)=512, K(W)=256
//
// GEMM: CTA tile 128x128, BK=16, 8 warps (64x32 warp tiles), double-buffered
// smem. Operands split in-register to tf32 big+small during gmem->smem copy;
// 3 mma passes (Ab*Bb, Ab*Bs, As*Bb) recover ~fp32 accuracy.

#define TT 500
#define BB 128
#define WW 256
#define FF 512
#define CC 10
#define MM (TT * BB)   // 64000

__device__ float g_proj[(size_t)MM * FF];   // 131 MB scratch

// ---------------------------------------------------------------------------
// helpers
// ---------------------------------------------------------------------------
__device__ __forceinline__ float tf32_rnd(float v) {
    uint32_t b;
    asm("cvt.rna.tf32.f32 %0, %1;" : "=r"(b) : "f"(v));
    return __uint_as_float(b);
}

// split float4 -> tf32 big/small, store as float4 to smem
__device__ __forceinline__ void split_store4(float4 v, float* big, float* small) {
    float vv[4] = {v.x, v.y, v.z, v.w};
    float b[4], s[4];
#pragma unroll
    for (int j = 0; j < 4; j++) {
        b[j] = tf32_rnd(vv[j]);
        s[j] = tf32_rnd(vv[j] - b[j]);
    }
    *reinterpret_cast<float4*>(big)   = make_float4(b[0], b[1], b[2], b[3]);
    *reinterpret_cast<float4*>(small) = make_float4(s[0], s[1], s[2], s[3]);
}

#define MMA_TF32(c, a, b) \
    asm volatile( \
        "mma.sync.aligned.m16n8k8.row.col.f32.tf32.tf32.f32 " \
        "{%0,%1,%2,%3}, {%4,%5,%6,%7}, {%8,%9}, {%0,%1,%2,%3};" \
        : "+f"((c)[0]), "+f"((c)[1]), "+f"((c)[2]), "+f"((c)[3]) \
        : "r"(__float_as_uint((a)[0])), "r"(__float_as_uint((a)[1])), \
          "r"(__float_as_uint((a)[2])), "r"(__float_as_uint((a)[3])), \
          "r"(__float_as_uint((b)[0])), "r"(__float_as_uint((b)[1])))

// ---------------------------------------------------------------------------
// GEMM kernel
// smem per stage (floats): Ab[128*20] As[128*20] Bb[128*20] Bs[128*20]
//   row stride 20 floats (16 data + 4 pad) -> conflict-free scalar LDS for
//   mma fragment patterns and 16B-aligned float4 STS.
// ---------------------------------------------------------------------------
#define ASTR 20
#define BUFF (128 * ASTR)          // 2560 floats per operand buffer
#define SS   (4 * BUFF)            // 10240 floats per stage
#define GEMM_SMEM (2 * SS * 4)     // 81920 bytes

__global__ __launch_bounds__(256, 1)
void gemm_mma_kernel(const float* __restrict__ X, const float* __restrict__ Wt) {
    extern __shared__ float sm[];
    const int tid  = threadIdx.x;
    const int lane = tid & 31;
    const int wid  = tid >> 5;
    const int warp_m = wid & 1;          // 0..1 -> 64-row slab
    const int warp_n = wid >> 1;         // 0..3 -> 32-col slab
    const int m0 = blockIdx.y * 128;
    const int n0 = blockIdx.x * 128;

    // gmem load mapping: thread -> rows rowL, rowL+64; 16-float chunk kq*4
    const int rowL = tid >> 2;           // 0..63
    const int kq   = tid & 3;
    const float* gA0 = X  + (size_t)(m0 + rowL) * WW + kq * 4;
    const float* gA1 = gA0 + (size_t)64 * WW;
    const float* gB0 = Wt + (size_t)(n0 + rowL) * WW + kq * 4;
    const float* gB1 = gB0 + (size_t)64 * WW;
    const int sto = rowL * ASTR + kq * 4;         // smem store offset (floats)
    const int sto64 = (rowL + 64) * ASTR + kq * 4;

    // fragment load offsets (floats)
    int aoff[4], boff[4];
#pragma unroll
    for (int mt = 0; mt < 4; mt++)
        aoff[mt] = (warp_m * 64 + mt * 16 + (lane >> 2)) * ASTR + (lane & 3);
#pragma unroll
    for (int nt = 0; nt < 4; nt++)
        boff[nt] = (warp_n * 32 + nt * 8 + (lane >> 2)) * ASTR + (lane & 3);

    float acc[4][4][4];
#pragma unroll
    for (int mt = 0; mt < 4; mt++)
#pragma unroll
        for (int nt = 0; nt < 4; nt++)
#pragma unroll
            for (int q = 0; q < 4; q++) acc[mt][nt][q] = 0.0f;

    // prologue: stage 0
    {
        float4 pa0 = *reinterpret_cast<const float4*>(gA0);
        float4 pa1 = *reinterpret_cast<const float4*>(gA1);
        float4 pb0 = *reinterpret_cast<const float4*>(gB0);
        float4 pb1 = *reinterpret_cast<const float4*>(gB1);
        split_store4(pa0, sm + sto,              sm + BUFF + sto);
        split_store4(pa1, sm + sto64,            sm + BUFF + sto64);
        split_store4(pb0, sm + 2 * BUFF + sto,   sm + 3 * BUFF + sto);
        split_store4(pb1, sm + 2 * BUFF + sto64, sm + 3 * BUFF + sto64);
    }
    __syncthreads();

    int buf = 0;
#pragma unroll 1
    for (int kt = 0; kt < 16; kt++) {
        const bool more = (kt < 15);
        float4 pa0, pa1, pb0, pb1;
        if (more) {
            pa0 = *reinterpret_cast<const float4*>(gA0 + (kt + 1) * 16);
            pa1 = *reinterpret_cast<const float4*>(gA1 + (kt + 1) * 16);
            pb0 = *reinterpret_cast<const float4*>(gB0 + (kt + 1) * 16);
            pb1 = *reinterpret_cast<const float4*>(gB1 + (kt + 1) * 16);
        }

        const float* Ab = sm + buf * SS;
        const float* As = Ab + BUFF;
        const float* Bb = Ab + 2 * BUFF;
        const float* Bs = Ab + 3 * BUFF;

#pragma unroll
        for (int ks = 0; ks < 2; ks++) {
            const int ko = ks * 8;
            float ab[4][4], asm_[4][4];
#pragma unroll
            for (int mt = 0; mt < 4; mt++) {
                const float* p = Ab + aoff[mt] + ko;
                const float* q = As + aoff[mt] + ko;
                ab[mt][0] = p[0];   ab[mt][1] = p[8 * ASTR];
                ab[mt][2] = p[4];   ab[mt][3] = p[8 * ASTR + 4];
                asm_[mt][0] = q[0]; asm_[mt][1] = q[8 * ASTR];
                asm_[mt][2] = q[4]; asm_[mt][3] = q[8 * ASTR + 4];
            }
            float bb[4][2], bs[4][2];
#pragma unroll
            for (int nt = 0; nt < 4; nt++) {
                const float* p = Bb + boff[nt] + ko;
                const float* q = Bs + boff[nt] + ko;
                bb[nt][0] = p[0]; bb[nt][1] = p[4];
                bs[nt][0] = q[0]; bs[nt][1] = q[4];
            }
#pragma unroll
            for (int mt = 0; mt < 4; mt++)
#pragma unroll
                for (int nt = 0; nt < 4; nt++) {
                    MMA_TF32(acc[mt][nt], ab[mt], bb[nt]);
                    MMA_TF32(acc[mt][nt], ab[mt], bs[nt]);
                    MMA_TF32(acc[mt][nt], asm_[mt], bb[nt]);
                }
        }

        if (more) {
            float* d = sm + (buf ^ 1) * SS;
            split_store4(pa0, d + sto,              d + BUFF + sto);
            split_store4(pa1, d + sto64,            d + BUFF + sto64);
            split_store4(pb0, d + 2 * BUFF + sto,   d + 3 * BUFF + sto);
            split_store4(pb1, d + 2 * BUFF + sto64, d + 3 * BUFF + sto64);
        }
        __syncthreads();
        buf ^= 1;
    }

    // epilogue: each warp writes its 64x32 tile; c0/c1 and c2/c3 are float2s
#pragma unroll
    for (int mt = 0; mt < 4; mt++) {
#pragma unroll
        for (int nt = 0; nt < 4; nt++) {
            const int r = m0 + warp_m * 64 + mt * 16 + (lane >> 2);
            const int c = n0 + warp_n * 32 + nt * 8 + (lane & 3) * 2;
            *reinterpret_cast<float2*>(&g_proj[(size_t)r * FF + c]) =
                make_float2(acc[mt][nt][0], acc[mt][nt][1]);
            *reinterpret_cast<float2*>(&g_proj[(size_t)(r + 8) * FF + c]) =
                make_float2(acc[mt][nt][2], acc[mt][nt][3]);
        }
    }
}

// ---------------------------------------------------------------------------
// LIF scan + fused decoder (unchanged from the 397us-passing kernel)
// ---------------------------------------------------------------------------
__global__ __launch_bounds__(512)
void scan_decoder_kernel(const float* __restrict__ dec_w,
                         const float* __restrict__ dec_b,
                         float* __restrict__ out) {
    const int b = blockIdx.x;
    const int f = threadIdx.x;
    const float* pp = g_proj + (size_t)b * FF + f;

    float u = 0.0f, trace = 0.0f, cnt = 0.0f;

#pragma unroll 1
    for (int t0 = 0; t0 < TT; t0 += 20) {
        float v[20];
#pragma unroll
        for (int i = 0; i < 20; i++)
            v[i] = pp[(size_t)(t0 + i) * (BB * FF)];
#pragma unroll
        for (int i = 0; i < 20; i++) {
            trace = 0.95f * trace + v[i];
            u = 0.9f * u + trace;
            if (u > 1.0f) { cnt += 1.0f; u = 0.0f; }
        }
    }

    __shared__ float sred[512];
    for (int c = 0; c < CC; c++) {
        sred[f] = cnt * dec_w[c * FF + f];
        __syncthreads();
#pragma unroll
        for (int s = 256; s > 0; s >>= 1) {
            if (f < s) sred[f] += sred[f + s];
            __syncthreads();
        }
        if (f == 0) out[b * CC + c] = sred[0] + dec_b[c];
        __syncthreads();
    }
}

// ---------------------------------------------------------------------------
extern "C" void kernel_launch(void* const* d_in, const int* in_sizes, int n_in,
                              void* d_out, int out_size) {
    const float* x     = (const float*)d_in[0];  // [500,128,256]
    const float* wts   = (const float*)d_in[1];  // [512,256]
    const float* dec_w = (const float*)d_in[2];  // [10,512]
    const float* dec_b = (const float*)d_in[3];  // [10]
    float* out = (float*)d_out;                  // [128,10]
    (void)in_sizes; (void)n_in; (void)out_size;

    cudaFuncSetAttribute(gemm_mma_kernel,
                         cudaFuncAttributeMaxDynamicSharedMemorySize, GEMM_SMEM);

    dim3 grid(FF / 128, MM / 128);   // (4, 500)
    gemm_mma_kernel<<<grid, 256, GEMM_SMEM>>>(x, wts);

    scan_decoder_kernel<<<BB, 512>>>(dec_w, dec_b, out);
}

// round 4
// speedup vs baseline: 1.5397x; 1.4375x over previous
#include <cuda_runtime.h>
#include <cuda_fp16.h>
#include <cstdint>

// FastSNN: fp32 GEMM via 2-term fp16 split x 4 exact products (mma.sync
// m16n8k16, ldmatrix fragments) -> LIF scan -> decoder.
// proj[m,f] = sum_w X[m,w]*Wt[f,w], M=64000, N(F)=512, K(W)=256.

#define TT 500
#define BB 128
#define WW 256
#define FF 512
#define CC 10
#define MM (TT * BB)

__device__ float g_proj[(size_t)MM * FF];   // 131 MB scratch

// ---------------------------------------------------------------------------
// smem layout: per stage, A then B; 128 rows each.
// Row = [big: 16 halves = 32B][small: 16 halves = 32B][pad 16B] -> 80B stride.
// LDSM phases hit rows r..r+7: word offsets r*20 mod 32 all-distinct 16B
// groups -> conflict-free ldmatrix.
// ---------------------------------------------------------------------------
#define RSTR 80                       // bytes per row
#define MATB (128 * RSTR)             // 10240 B per matrix
#define STAGEB (2 * MATB)             // 20480 B per stage (A + B)

__device__ __forceinline__ uint32_t smem_u32(const void* p) {
    uint32_t a;
    asm("{ .reg .u64 t; cvta.to.shared.u64 t, %1; cvt.u32.u64 %0, t; }" : "=r"(a) : "l"(p));
    return a;
}

#define LDSM_X4(r0, r1, r2, r3, addr) \
    asm volatile("ldmatrix.sync.aligned.m8n8.x4.shared.b16 {%0,%1,%2,%3}, [%4];" \
        : "=r"(r0), "=r"(r1), "=r"(r2), "=r"(r3) : "r"(addr))

#define MMA_F16(c, a, b) \
    asm volatile( \
        "mma.sync.aligned.m16n8k16.row.col.f32.f16.f16.f32 " \
        "{%0,%1,%2,%3}, {%4,%5,%6,%7}, {%8,%9}, {%0,%1,%2,%3};" \
        : "+f"((c)[0]), "+f"((c)[1]), "+f"((c)[2]), "+f"((c)[3]) \
        : "r"((a)[0]), "r"((a)[1]), "r"((a)[2]), "r"((a)[3]), \
          "r"((b)[0]), "r"((b)[1]))

// convert 8 fp32 -> 8 big halves (uint4) + 8 small halves (uint4)
__device__ __forceinline__ void cvt8(const float4 v0, const float4 v1,
                                     uint4& big, uint4& small) {
    float v[8] = {v0.x, v0.y, v0.z, v0.w, v1.x, v1.y, v1.z, v1.w};
    __half hb[8], hs[8];
#pragma unroll
    for (int j = 0; j < 8; j++) {
        hb[j] = __float2half_rn(v[j]);
        hs[j] = __float2half_rn(v[j] - __half2float(hb[j]));
    }
    __half2 b2[4], s2[4];
#pragma unroll
    for (int j = 0; j < 4; j++) {
        b2[j] = __halves2half2(hb[2*j], hb[2*j+1]);
        s2[j] = __halves2half2(hs[2*j], hs[2*j+1]);
    }
    big   = make_uint4(*(uint32_t*)&b2[0], *(uint32_t*)&b2[1],
                       *(uint32_t*)&b2[2], *(uint32_t*)&b2[3]);
    small = make_uint4(*(uint32_t*)&s2[0], *(uint32_t*)&s2[1],
                       *(uint32_t*)&s2[2], *(uint32_t*)&s2[3]);
}

// ---------------------------------------------------------------------------
// GEMM: CTA 128x128, BK=16, 256 threads = 8 warps in 2(m) x 4(n), warp tile
// 64x32. Double-buffered smem; 4 fp16 product passes per (mt,nt) per kt.
// ---------------------------------------------------------------------------
__global__ __launch_bounds__(256)
void gemm_fp16_kernel(const float* __restrict__ X, const float* __restrict__ Wt) {
    __shared__ __align__(128) char sm[2 * STAGEB];   // 40 KB

    const int tid  = threadIdx.x;
    const int lane = tid & 31;
    const int wid  = tid >> 5;
    const int warp_m = wid & 1;
    const int warp_n = wid >> 1;
    const int m0 = blockIdx.y * 128;
    const int n0 = blockIdx.x * 128;

    const uint32_t sbase = smem_u32(sm);

    // gmem copy mapping: thread -> (row = tid>>1, kh = tid&1); 8 fp32 per matrix
    const int rowC = tid >> 1;
    const int kh   = tid & 1;
    const float* gA = X  + (size_t)(m0 + rowC) * WW + kh * 8;
    const float* gB = Wt + (size_t)(n0 + rowC) * WW + kh * 8;
    const uint32_t stoA = rowC * RSTR + kh * 16;          // big; +32 for small
    const uint32_t stoB = MATB + stoA;

    // ldmatrix lane addressing
    const uint32_t lrow  = lane & 15;
    const uint32_t lkoff = ((lane >> 4) & 1) * 16;
    const uint32_t aAddr0 = (warp_m * 64 + lrow) * RSTR + lkoff;          // + mt*16*RSTR
    const uint32_t bAddr0 = MATB + (warp_n * 32 + lrow) * RSTR + lkoff;   // + p*16*RSTR

    float acc[4][4][4];
#pragma unroll
    for (int mt = 0; mt < 4; mt++)
#pragma unroll
        for (int nt = 0; nt < 4; nt++)
#pragma unroll
            for (int q = 0; q < 4; q++) acc[mt][nt][q] = 0.0f;

    // prologue: fill stage 0
    {
        float4 a0 = *(const float4*)(gA);
        float4 a1 = *(const float4*)(gA + 4);
        float4 b0 = *(const float4*)(gB);
        float4 b1 = *(const float4*)(gB + 4);
        uint4 big, small;
        cvt8(a0, a1, big, small);
        *(uint4*)(sm + stoA)      = big;
        *(uint4*)(sm + stoA + 32) = small;
        cvt8(b0, b1, big, small);
        *(uint4*)(sm + stoB)      = big;
        *(uint4*)(sm + stoB + 32) = small;
    }
    __syncthreads();

    int buf = 0;
#pragma unroll 1
    for (int kt = 0; kt < 16; kt++) {
        const bool more = (kt < 15);
        float4 pa0, pa1, pb0, pb1;
        if (more) {
            const int ko = (kt + 1) * 16;
            pa0 = *(const float4*)(gA + ko);
            pa1 = *(const float4*)(gA + ko + 4);
            pb0 = *(const float4*)(gB + ko);
            pb1 = *(const float4*)(gB + ko + 4);
        }

        const uint32_t sb = sbase + buf * STAGEB;

        // load fragments
        uint32_t ab[4][4], as_[4][4], bb[4][2], bs[4][2];
#pragma unroll
        for (int mt = 0; mt < 4; mt++) {
            const uint32_t ad = sb + aAddr0 + mt * 16 * RSTR;
            LDSM_X4(ab[mt][0],  ab[mt][1],  ab[mt][2],  ab[mt][3],  ad);
            LDSM_X4(as_[mt][0], as_[mt][1], as_[mt][2], as_[mt][3], ad + 32);
        }
#pragma unroll
        for (int p = 0; p < 2; p++) {
            const uint32_t bd = sb + bAddr0 + p * 16 * RSTR;
            uint32_t r0, r1, r2, r3;
            LDSM_X4(r0, r1, r2, r3, bd);
            bb[2*p][0] = r0; bb[2*p][1] = r2;
            bb[2*p+1][0] = r1; bb[2*p+1][1] = r3;
            LDSM_X4(r0, r1, r2, r3, bd + 32);
            bs[2*p][0] = r0; bs[2*p][1] = r2;
            bs[2*p+1][0] = r1; bs[2*p+1][1] = r3;
        }

        // 4 exact products: Ab*Bb + Ab*Bs + As*Bb + As*Bs
#pragma unroll
        for (int mt = 0; mt < 4; mt++)
#pragma unroll
            for (int nt = 0; nt < 4; nt++) {
                MMA_F16(acc[mt][nt], ab[mt],  bb[nt]);
                MMA_F16(acc[mt][nt], ab[mt],  bs[nt]);
                MMA_F16(acc[mt][nt], as_[mt], bb[nt]);
                MMA_F16(acc[mt][nt], as_[mt], bs[nt]);
            }

        if (more) {
            char* d = sm + (buf ^ 1) * STAGEB;
            uint4 big, small;
            cvt8(pa0, pa1, big, small);
            *(uint4*)(d + stoA)      = big;
            *(uint4*)(d + stoA + 32) = small;
            cvt8(pb0, pb1, big, small);
            *(uint4*)(d + stoB)      = big;
            *(uint4*)(d + stoB + 32) = small;
        }
        __syncthreads();
        buf ^= 1;
    }

    // epilogue
#pragma unroll
    for (int mt = 0; mt < 4; mt++) {
#pragma unroll
        for (int nt = 0; nt < 4; nt++) {
            const int r = m0 + warp_m * 64 + mt * 16 + (lane >> 2);
            const int c = n0 + warp_n * 32 + nt * 8 + (lane & 3) * 2;
            *reinterpret_cast<float2*>(&g_proj[(size_t)r * FF + c]) =
                make_float2(acc[mt][nt][0], acc[mt][nt][1]);
            *reinterpret_cast<float2*>(&g_proj[(size_t)(r + 8) * FF + c]) =
                make_float2(acc[mt][nt][2], acc[mt][nt][3]);
        }
    }
}

// ---------------------------------------------------------------------------
// LIF scan + fused decoder (unchanged)
// ---------------------------------------------------------------------------
__global__ __launch_bounds__(512)
void scan_decoder_kernel(const float* __restrict__ dec_w,
                         const float* __restrict__ dec_b,
                         float* __restrict__ out) {
    const int b = blockIdx.x;
    const int f = threadIdx.x;
    const float* pp = g_proj + (size_t)b * FF + f;

    float u = 0.0f, trace = 0.0f, cnt = 0.0f;

#pragma unroll 1
    for (int t0 = 0; t0 < TT; t0 += 20) {
        float v[20];
#pragma unroll
        for (int i = 0; i < 20; i++)
            v[i] = pp[(size_t)(t0 + i) * (BB * FF)];
#pragma unroll
        for (int i = 0; i < 20; i++) {
            trace = 0.95f * trace + v[i];
            u = 0.9f * u + trace;
            if (u > 1.0f) { cnt += 1.0f; u = 0.0f; }
        }
    }

    __shared__ float sred[512];
    for (int c = 0; c < CC; c++) {
        sred[f] = cnt * dec_w[c * FF + f];
        __syncthreads();
#pragma unroll
        for (int s = 256; s > 0; s >>= 1) {
            if (f < s) sred[f] += sred[f + s];
            __syncthreads();
        }
        if (f == 0) out[b * CC + c] = sred[0] + dec_b[c];
        __syncthreads();
    }
}

// ---------------------------------------------------------------------------
extern "C" void kernel_launch(void* const* d_in, const int* in_sizes, int n_in,
                              void* d_out, int out_size) {
    const float* x     = (const float*)d_in[0];  // [500,128,256]
    const float* wts   = (const float*)d_in[1];  // [512,256]
    const float* dec_w = (const float*)d_in[2];  // [10,512]
    const float* dec_b = (const float*)d_in[3];  // [10]
    float* out = (float*)d_out;                  // [128,10]
    (void)in_sizes; (void)n_in; (void)out_size;

    dim3 grid(FF / 128, MM / 128);   // (4, 500)
    gemm_fp16_kernel<<<grid, 256>>>(x, wts);

    scan_decoder_kernel<<<BB, 512>>>(dec_w, dec_b, out);
}

// round 5
// speedup vs baseline: 1.7436x; 1.1324x over previous
#include <cuda_runtime.h>
#include <cuda_fp16.h>
#include <cstdint>

// FastSNN: fp32 GEMM via 2-term fp16 split x 3 products (a0b0+a0b1+a1b0;
// dropped a1b1 term is <= 2^-22 rel) using mma.sync m16n8k16 + ldmatrix.
// proj[m,f] = sum_w X[m,w]*Wt[f,w], M=64000, N(F)=512, K(W)=256.
// Then LIF scan over T + decoder.

#define TT 500
#define BB 128
#define WW 256
#define FF 512
#define CC 10
#define MM (TT * BB)

__device__ float g_proj[(size_t)MM * FF];   // 131 MB scratch

// ---------------------------------------------------------------------------
// smem: per stage A then B, 128 rows each.
// Row = [big 32B][small 32B][pad 16B] -> 80B stride (conflict-free ldmatrix).
// ---------------------------------------------------------------------------
#define RSTR 80
#define MATB (128 * RSTR)
#define STAGEB (2 * MATB)             // 20480 B per stage

__device__ __forceinline__ uint32_t smem_u32(const void* p) {
    uint32_t a;
    asm("{ .reg .u64 t; cvta.to.shared.u64 t, %1; cvt.u32.u64 %0, t; }" : "=r"(a) : "l"(p));
    return a;
}

#define LDSM_X4(r0, r1, r2, r3, addr) \
    asm volatile("ldmatrix.sync.aligned.m8n8.x4.shared.b16 {%0,%1,%2,%3}, [%4];" \
        : "=r"(r0), "=r"(r1), "=r"(r2), "=r"(r3) : "r"(addr))

#define MMA_F16(c, a, b) \
    asm volatile( \
        "mma.sync.aligned.m16n8k16.row.col.f32.f16.f16.f32 " \
        "{%0,%1,%2,%3}, {%4,%5,%6,%7}, {%8,%9}, {%0,%1,%2,%3};" \
        : "+f"((c)[0]), "+f"((c)[1]), "+f"((c)[2]), "+f"((c)[3]) \
        : "r"((a)[0]), "r"((a)[1]), "r"((a)[2]), "r"((a)[3]), \
          "r"((b)[0]), "r"((b)[1]))

__device__ __forceinline__ void cvt8(const float4 v0, const float4 v1,
                                     uint4& big, uint4& small) {
    float v[8] = {v0.x, v0.y, v0.z, v0.w, v1.x, v1.y, v1.z, v1.w};
    __half hb[8], hs[8];
#pragma unroll
    for (int j = 0; j < 8; j++) {
        hb[j] = __float2half_rn(v[j]);
        hs[j] = __float2half_rn(v[j] - __half2float(hb[j]));
    }
    __half2 b2[4], s2[4];
#pragma unroll
    for (int j = 0; j < 4; j++) {
        b2[j] = __halves2half2(hb[2*j], hb[2*j+1]);
        s2[j] = __halves2half2(hs[2*j], hs[2*j+1]);
    }
    big   = make_uint4(*(uint32_t*)&b2[0], *(uint32_t*)&b2[1],
                       *(uint32_t*)&b2[2], *(uint32_t*)&b2[3]);
    small = make_uint4(*(uint32_t*)&s2[0], *(uint32_t*)&s2[1],
                       *(uint32_t*)&s2[2], *(uint32_t*)&s2[3]);
}

// ---------------------------------------------------------------------------
// GEMM: CTA 128x128, BK=16, 8 warps (2m x 4n), warp tile 64x32, double-buffer.
// ---------------------------------------------------------------------------
__global__ __launch_bounds__(256, 2)
void gemm_fp16_kernel(const float* __restrict__ X, const float* __restrict__ Wt) {
    __shared__ __align__(128) char sm[2 * STAGEB];   // 40 KB

    const int tid  = threadIdx.x;
    const int lane = tid & 31;
    const int wid  = tid >> 5;
    const int warp_m = wid & 1;
    const int warp_n = wid >> 1;
    const int m0 = blockIdx.y * 128;
    const int n0 = blockIdx.x * 128;

    const uint32_t sbase = smem_u32(sm);

    const int rowC = tid >> 1;
    const int kh   = tid & 1;
    const float* gA = X  + (size_t)(m0 + rowC) * WW + kh * 8;
    const float* gB = Wt + (size_t)(n0 + rowC) * WW + kh * 8;
    const uint32_t stoA = rowC * RSTR + kh * 16;
    const uint32_t stoB = MATB + stoA;

    const uint32_t lrow  = lane & 15;
    const uint32_t lkoff = ((lane >> 4) & 1) * 16;
    const uint32_t aAddr0 = (warp_m * 64 + lrow) * RSTR + lkoff;
    const uint32_t bAddr0 = MATB + (warp_n * 32 + lrow) * RSTR + lkoff;

    float acc[4][4][4];
#pragma unroll
    for (int mt = 0; mt < 4; mt++)
#pragma unroll
        for (int nt = 0; nt < 4; nt++)
#pragma unroll
            for (int q = 0; q < 4; q++) acc[mt][nt][q] = 0.0f;

    {
        float4 a0 = *(const float4*)(gA);
        float4 a1 = *(const float4*)(gA + 4);
        float4 b0 = *(const float4*)(gB);
        float4 b1 = *(const float4*)(gB + 4);
        uint4 big, small;
        cvt8(a0, a1, big, small);
        *(uint4*)(sm + stoA)      = big;
        *(uint4*)(sm + stoA + 32) = small;
        cvt8(b0, b1, big, small);
        *(uint4*)(sm + stoB)      = big;
        *(uint4*)(sm + stoB + 32) = small;
    }
    __syncthreads();

    int buf = 0;
#pragma unroll 1
    for (int kt = 0; kt < 16; kt++) {
        const bool more = (kt < 15);
        float4 pa0, pa1, pb0, pb1;
        if (more) {
            const int ko = (kt + 1) * 16;
            pa0 = *(const float4*)(gA + ko);
            pa1 = *(const float4*)(gA + ko + 4);
            pb0 = *(const float4*)(gB + ko);
            pb1 = *(const float4*)(gB + ko + 4);
        }

        const uint32_t sb = sbase + buf * STAGEB;

        uint32_t ab[4][4], as_[4][4], bb[4][2], bs[4][2];
#pragma unroll
        for (int mt = 0; mt < 4; mt++) {
            const uint32_t ad = sb + aAddr0 + mt * 16 * RSTR;
            LDSM_X4(ab[mt][0],  ab[mt][1],  ab[mt][2],  ab[mt][3],  ad);
            LDSM_X4(as_[mt][0], as_[mt][1], as_[mt][2], as_[mt][3], ad + 32);
        }
#pragma unroll
        for (int p = 0; p < 2; p++) {
            const uint32_t bd = sb + bAddr0 + p * 16 * RSTR;
            uint32_t r0, r1, r2, r3;
            LDSM_X4(r0, r1, r2, r3, bd);
            bb[2*p][0] = r0; bb[2*p][1] = r2;
            bb[2*p+1][0] = r1; bb[2*p+1][1] = r3;
            LDSM_X4(r0, r1, r2, r3, bd + 32);
            bs[2*p][0] = r0; bs[2*p][1] = r2;
            bs[2*p+1][0] = r1; bs[2*p+1][1] = r3;
        }

        // 3 products: a0b0 + a0b1 + a1b0   (a1b1 dropped, <=2^-22 rel)
#pragma unroll
        for (int mt = 0; mt < 4; mt++)
#pragma unroll
            for (int nt = 0; nt < 4; nt++) {
                MMA_F16(acc[mt][nt], ab[mt],  bb[nt]);
                MMA_F16(acc[mt][nt], ab[mt],  bs[nt]);
                MMA_F16(acc[mt][nt], as_[mt], bb[nt]);
            }

        if (more) {
            char* d = sm + (buf ^ 1) * STAGEB;
            uint4 big, small;
            cvt8(pa0, pa1, big, small);
            *(uint4*)(d + stoA)      = big;
            *(uint4*)(d + stoA + 32) = small;
            cvt8(pb0, pb1, big, small);
            *(uint4*)(d + stoB)      = big;
            *(uint4*)(d + stoB + 32) = small;
        }
        __syncthreads();
        buf ^= 1;
    }

#pragma unroll
    for (int mt = 0; mt < 4; mt++) {
#pragma unroll
        for (int nt = 0; nt < 4; nt++) {
            const int r = m0 + warp_m * 64 + mt * 16 + (lane >> 2);
            const int c = n0 + warp_n * 32 + nt * 8 + (lane & 3) * 2;
            *reinterpret_cast<float2*>(&g_proj[(size_t)r * FF + c]) =
                make_float2(acc[mt][nt][0], acc[mt][nt][1]);
            *reinterpret_cast<float2*>(&g_proj[(size_t)(r + 8) * FF + c]) =
                make_float2(acc[mt][nt][2], acc[mt][nt][3]);
        }
    }
}

// ---------------------------------------------------------------------------
// LIF scan + fused decoder
// ---------------------------------------------------------------------------
__global__ __launch_bounds__(512)
void scan_decoder_kernel(const float* __restrict__ dec_w,
                         const float* __restrict__ dec_b,
                         float* __restrict__ out) {
    const int b = blockIdx.x;
    const int f = threadIdx.x;
    const float* pp = g_proj + (size_t)b * FF + f;

    float u = 0.0f, trace = 0.0f, cnt = 0.0f;

#pragma unroll 1
    for (int t0 = 0; t0 < TT; t0 += 20) {
        float v[20];
#pragma unroll
        for (int i = 0; i < 20; i++)
            v[i] = pp[(size_t)(t0 + i) * (BB * FF)];
#pragma unroll
        for (int i = 0; i < 20; i++) {
            trace = 0.95f * trace + v[i];
            u = 0.9f * u + trace;
            if (u > 1.0f) { cnt += 1.0f; u = 0.0f; }
        }
    }

    __shared__ float sred[512];
    for (int c = 0; c < CC; c++) {
        sred[f] = cnt * dec_w[c * FF + f];
        __syncthreads();
#pragma unroll
        for (int s = 256; s > 0; s >>= 1) {
            if (f < s) sred[f] += sred[f + s];
            __syncthreads();
        }
        if (f == 0) out[b * CC + c] = sred[0] + dec_b[c];
        __syncthreads();
    }
}

// ---------------------------------------------------------------------------
extern "C" void kernel_launch(void* const* d_in, const int* in_sizes, int n_in,
                              void* d_out, int out_size) {
    const float* x     = (const float*)d_in[0];  // [500,128,256]
    const float* wts   = (const float*)d_in[1];  // [512,256]
    const float* dec_w = (const float*)d_in[2];  // [10,512]
    const float* dec_b = (const float*)d_in[3];  // [10]
    float* out = (float*)d_out;                  // [128,10]
    (void)in_sizes; (void)n_in; (void)out_size;

    dim3 grid(FF / 128, MM / 128);   // (4, 500)
    gemm_fp16_kernel<<<grid, 256>>>(x, wts);

    scan_decoder_kernel<<<BB, 512>>>(dec_w, dec_b, out);
}